// round 16
// baseline (speedup 1.0000x reference)
#include <cuda_runtime.h>
#include <cuda_fp16.h>
#include <cstdint>

#define NN 50000
#define NE 800000
#define NG 64
#define H  128
#define CL 16
#define ODIM 128
#define PAD 72    // padded CSR row capacity; non-power-of-2 stride (288 B)

// ---------------- scratch (device globals; no allocation allowed) ----------------
__device__ uint2 g_xh[NN * 32];     // fp16: embedding input, later final normalized x
__device__ uint2 g_yh[NN * 32];     // fp16 pre-norm GEMM output
__device__ uint2 g_mh[NN * 32];     // fp16 aggregated means (already normalized inputs)
__device__ int   g_deg[NN];         // atomic counter -> final in-degree
__device__ int   g_csrp[NN * PAD];  // padded CSR: PREMULTIPLIED (src*32) row offsets
__device__ float g_scores[NN * CL];
__device__ int   g_goff[NG + 1];
__device__ float g_stats[3 * 256];  // per-layer sum/sumsq slots
__device__ float g_clust[NG * CL * H];
__device__ float g_pmax[NG * CL];
__device__ float g_pinv[NG * CL];
// weights fp16, transposed, packed as u32 pairs along k:
// layout [layer][n][kpair]  (kpair = k/2, 128 pairs, k<128 -> Wl^T, k>=128 -> Wr^T)
__device__ uint32_t g_wth[3 * 128 * 128];

// ---------------- helpers ----------------
__device__ __forceinline__ void mma_f16(float* c, const uint32_t* a, const uint32_t* b) {
    asm volatile(
        "mma.sync.aligned.m16n8k16.row.col.f32.f16.f16.f32 "
        "{%0,%1,%2,%3}, {%4,%5,%6,%7}, {%8,%9}, {%0,%1,%2,%3};"
        : "+f"(c[0]), "+f"(c[1]), "+f"(c[2]), "+f"(c[3])
        : "r"(a[0]), "r"(a[1]), "r"(a[2]), "r"(a[3]), "r"(b[0]), "r"(b[1]));
}

__device__ __forceinline__ uint2 f4_to_h4(float4 v) {
    uint2 u;
    __half2 a = __floats2half2_rn(v.x, v.y);
    __half2 b = __floats2half2_rn(v.z, v.w);
    u.x = *(uint32_t*)&a;
    u.y = *(uint32_t*)&b;
    return u;
}
__device__ __forceinline__ float4 h4_to_f4(uint2 u) {
    float2 a = __half22float2(*(__half2*)&u.x);
    float2 b = __half22float2(*(__half2*)&u.y);
    return make_float4(a.x, a.y, b.x, b.y);
}

// ---------------- merged preamble: embed | scatter(padded CSR) | goff | prep ----------------
#define B_EMBED 6250
#define B_SCAT  3125
#define B_GOFF  196
#define B_PREP  192

__global__ void __launch_bounds__(256) k_pre(const float* __restrict__ emb,
                                             const int* __restrict__ degidx,
                                             const int* __restrict__ src,
                                             const int* __restrict__ dst,
                                             const int* __restrict__ batch,
                                             const float* __restrict__ Wl,
                                             const float* __restrict__ Wr,
                                             int n, int e) {
    int b = blockIdx.x, t = threadIdx.x;
    if (b < B_EMBED) {
        int i = b * 256 + t;
        if (i < n * 32) {
            int node = i >> 5, q = i & 31;
            int d = degidx[node];
            float4 v = ((const float4*)(emb + (size_t)d * H))[q];
            g_xh[i] = f4_to_h4(v);
        }
    } else if (b < B_EMBED + B_SCAT) {
        int i = (b - B_EMBED) * 256 + t;
        if (i < e) {
            int d = dst[i];
            int p = atomicAdd(&g_deg[d], 1);
            if (p < PAD) g_csrp[d * PAD + p] = src[i] * 32;   // premultiplied row offset
        }
    } else if (b < B_EMBED + B_SCAT + B_GOFF) {
        int i = (b - B_EMBED - B_SCAT) * 256 + t;
        if (i < n) {
            int bb = batch[i];
            int bp = (i == 0) ? -1 : batch[i - 1];
            for (int g = bp + 1; g <= bb; g++) g_goff[g] = i;
            if (i == n - 1) {
                for (int g = bb + 1; g <= NG; g++) g_goff[g] = n;
            }
        }
    } else {
        int i = (b - B_EMBED - B_SCAT - B_GOFF) * 256 + t;
        if (i < 3 * 128 * 128) {
            int l = i >> 14, r = i & 16383, nn = r >> 7, kp = r & 127;
            int k = kp * 2;
            float v0, v1;
            if (k < 128) {
                v0 = Wl[l * 16384 + k * 128 + nn];
                v1 = Wl[l * 16384 + (k + 1) * 128 + nn];
            } else {
                v0 = Wr[l * 16384 + (k - 128) * 128 + nn];
                v1 = Wr[l * 16384 + (k - 127) * 128 + nn];
            }
            __half2 h = __floats2half2_rn(v0, v1);
            g_wth[i] = *(uint32_t*)&h;
        }
    }
}

// ---------------- mean aggregation: warp per node, shfl-distributed indices ----------------
__global__ void __launch_bounds__(256, 5) k_agg(const float* __restrict__ gamma,
                                                const float* __restrict__ beta,
                                                int layer, int n) {
    int w    = (blockIdx.x * blockDim.x + threadIdx.x) >> 5;
    int lane = threadIdx.x & 31;
    if (w >= n) return;
    int deg = g_deg[w];
    if (deg > PAD) deg = PAD;
    const int* nb = &g_csrp[w * PAD];
    float4 acc0 = make_float4(0.f, 0.f, 0.f, 0.f);
    float4 acc1 = make_float4(0.f, 0.f, 0.f, 0.f);

    if (layer == 0) {
        const uint2* xh = g_xh;
        for (int base = 0; base < deg; base += 32) {
            int cnt = deg - base; if (cnt > 32) cnt = 32;
            int idx = (base + lane < deg) ? __ldg(&nb[base + lane]) : 0;
            int j = 0;
            for (; j + 1 < cnt; j += 2) {
                int s0 = __shfl_sync(0xffffffffu, idx, j);
                int s1 = __shfl_sync(0xffffffffu, idx, j + 1);
                float4 a = h4_to_f4(__ldg(&xh[s0 + lane]));
                float4 b = h4_to_f4(__ldg(&xh[s1 + lane]));
                acc0.x += a.x; acc0.y += a.y; acc0.z += a.z; acc0.w += a.w;
                acc1.x += b.x; acc1.y += b.y; acc1.z += b.z; acc1.w += b.w;
            }
            if (j < cnt) {
                int s0 = __shfl_sync(0xffffffffu, idx, j);
                float4 a = h4_to_f4(__ldg(&xh[s0 + lane]));
                acc0.x += a.x; acc0.y += a.y; acc0.z += a.z; acc0.w += a.w;
            }
        }
    } else {
        const float* st = g_stats + (layer - 1) * 256;
        float invn = 1.f / (float)n;
        int c0 = lane * 4;
        float sc[4], sh[4];
        #pragma unroll
        for (int j = 0; j < 4; j++) {
            float mu  = st[c0 + j] * invn;
            float var = st[128 + c0 + j] * invn - mu * mu;
            float s   = rsqrtf(var + 1e-5f) * gamma[c0 + j];
            sc[j] = s;
            sh[j] = beta[c0 + j] - mu * s;
        }
        const uint2* yh = g_yh;
        for (int base = 0; base < deg; base += 32) {
            int cnt = deg - base; if (cnt > 32) cnt = 32;
            int idx = (base + lane < deg) ? __ldg(&nb[base + lane]) : 0;
            int j = 0;
            for (; j + 1 < cnt; j += 2) {
                int s0 = __shfl_sync(0xffffffffu, idx, j);
                int s1 = __shfl_sync(0xffffffffu, idx, j + 1);
                float4 a = h4_to_f4(__ldg(&yh[s0 + lane]));
                float4 b = h4_to_f4(__ldg(&yh[s1 + lane]));
                acc0.x += fmaxf(a.x * sc[0] + sh[0], 0.f);
                acc0.y += fmaxf(a.y * sc[1] + sh[1], 0.f);
                acc0.z += fmaxf(a.z * sc[2] + sh[2], 0.f);
                acc0.w += fmaxf(a.w * sc[3] + sh[3], 0.f);
                acc1.x += fmaxf(b.x * sc[0] + sh[0], 0.f);
                acc1.y += fmaxf(b.y * sc[1] + sh[1], 0.f);
                acc1.z += fmaxf(b.z * sc[2] + sh[2], 0.f);
                acc1.w += fmaxf(b.w * sc[3] + sh[3], 0.f);
            }
            if (j < cnt) {
                int s0 = __shfl_sync(0xffffffffu, idx, j);
                float4 a = h4_to_f4(__ldg(&yh[s0 + lane]));
                acc0.x += fmaxf(a.x * sc[0] + sh[0], 0.f);
                acc0.y += fmaxf(a.y * sc[1] + sh[1], 0.f);
                acc0.z += fmaxf(a.z * sc[2] + sh[2], 0.f);
                acc0.w += fmaxf(a.w * sc[3] + sh[3], 0.f);
            }
        }
    }
    acc0.x += acc1.x; acc0.y += acc1.y; acc0.z += acc1.z; acc0.w += acc1.w;
    float inv = 1.f / (float)(deg > 1 ? deg : 1);
    acc0.x *= inv; acc0.y *= inv; acc0.z *= inv; acc0.w *= inv;
    g_mh[w * 32 + lane] = f4_to_h4(acc0);
}

// ---------------- mma.sync fp16 GEMM: A exact fp16, B fp16 (single plane) ----------------
#define WST 72
#define PLANE (128 * WST)
#define GEMM_SMEM_MMA (2 * PLANE * 2 + 256 * 4 + 128 * 4 + 256 * 4)

__global__ void __launch_bounds__(256, 2) k_gemm_mma(const float* __restrict__ bl,
                                                     const float* __restrict__ gamma,
                                                     const float* __restrict__ beta,
                                                     int layer, int n) {
    extern __shared__ char smraw[];
    __half* As = (__half*)smraw;
    __half* Bs = As + PLANE;
    float* sred   = (float*)(Bs + PLANE);   // [256]
    float* sbias  = sred + 256;             // [128]
    float* sscale = sbias + 128;            // [128]
    float* sshift = sscale + 128;           // [128]

    int t = threadIdx.x, lane = t & 31, wid = t >> 5;
    int gq = lane >> 2, tig = lane & 3;
    int rowBase = blockIdx.x * 128;
    int m0 = (wid >> 2) * 64, n0 = (wid & 3) * 32;
    const uint32_t* wth = g_wth + layer * 16384;

    if (t < 128) {
        sbias[t] = bl[t];
        if (layer > 0) {
            const float* st = g_stats + (layer - 1) * 256;
            float invn = 1.f / (float)n;
            float mu  = st[t] * invn;
            float var = st[128 + t] * invn - mu * mu;
            float s   = rsqrtf(var + 1e-5f) * gamma[t];
            sscale[t] = s;
            sshift[t] = beta[t] - mu * s;
        }
    }
    sred[t] = 0.f;

    float acc[4][4][4];
    #pragma unroll
    for (int mt = 0; mt < 4; mt++)
        #pragma unroll
        for (int nt = 0; nt < 4; nt++)
            #pragma unroll
            for (int q = 0; q < 4; q++) acc[mt][nt][q] = 0.f;

    for (int chunk = 0; chunk < 4; chunk++) {
        int qoff = (chunk & 1) * 16;
        __syncthreads();
        #pragma unroll
        for (int it = 0; it < 8; it++) {
            int f = t + it * 256;            // 0..2047
            int row = f >> 4, qi = f & 15;
            int grow = rowBase + row;
            uint2 u = make_uint2(0u, 0u);
            if (chunk < 2) {
                if (grow < n) u = g_mh[grow * 32 + qoff + qi];
            } else if (layer == 0) {
                if (grow < n) u = g_xh[grow * 32 + qoff + qi];
            } else {
                if (grow < n) u = g_yh[grow * 32 + qoff + qi];
                float4 v = h4_to_f4(u);
                int c0 = (qoff + qi) * 4;
                v.x = fmaxf(v.x * sscale[c0 + 0] + sshift[c0 + 0], 0.f);
                v.y = fmaxf(v.y * sscale[c0 + 1] + sshift[c0 + 1], 0.f);
                v.z = fmaxf(v.z * sscale[c0 + 2] + sshift[c0 + 2], 0.f);
                v.w = fmaxf(v.w * sscale[c0 + 3] + sshift[c0 + 3], 0.f);
                u = f4_to_h4(v);
            }
            int kc = qi * 4;
            *(uint2*)&As[row * WST + kc] = u;
            *(uint2*)&Bs[row * WST + kc] = *(const uint2*)&wth[row * 128 + chunk * 32 + qi * 2];
        }
        __syncthreads();

        #pragma unroll
        for (int ks = 0; ks < 4; ks++) {
            int kb = ks * 16;
            uint32_t bfr[4][2];
            #pragma unroll
            for (int nt = 0; nt < 4; nt++) {
                int brow = n0 + nt * 8 + gq;
                int kc = kb + tig * 2;
                bfr[nt][0] = *(const uint32_t*)&Bs[brow * WST + kc];
                bfr[nt][1] = *(const uint32_t*)&Bs[brow * WST + kc + 8];
            }
            #pragma unroll
            for (int mt = 0; mt < 4; mt++) {
                int arow = m0 + mt * 16 + gq;
                int kc = kb + tig * 2;
                uint32_t a[4];
                a[0] = *(const uint32_t*)&As[arow * WST + kc];
                a[1] = *(const uint32_t*)&As[(arow + 8) * WST + kc];
                a[2] = *(const uint32_t*)&As[arow * WST + kc + 8];
                a[3] = *(const uint32_t*)&As[(arow + 8) * WST + kc + 8];
                #pragma unroll
                for (int nt = 0; nt < 4; nt++) {
                    mma_f16(acc[mt][nt], a, bfr[nt]);
                }
            }
        }
    }

    // epilogue: bias add, store y (fp16), batchnorm partial stats (fp32 exact)
    float cs[4][2], cq[4][2];
    #pragma unroll
    for (int nt = 0; nt < 4; nt++) { cs[nt][0] = cs[nt][1] = cq[nt][0] = cq[nt][1] = 0.f; }
    #pragma unroll
    for (int mt = 0; mt < 4; mt++) {
        #pragma unroll
        for (int r = 0; r < 2; r++) {
            int row = rowBase + m0 + mt * 16 + gq + r * 8;
            if (row < n) {
                #pragma unroll
                for (int nt = 0; nt < 4; nt++) {
                    int col = n0 + nt * 8 + tig * 2;
                    float y0 = acc[mt][nt][r * 2 + 0] + sbias[col];
                    float y1 = acc[mt][nt][r * 2 + 1] + sbias[col + 1];
                    __half2 hp = __floats2half2_rn(y0, y1);
                    ((uint32_t*)g_yh)[(size_t)row * 64 + (col >> 1)] = *(uint32_t*)&hp;
                    cs[nt][0] += y0; cs[nt][1] += y1;
                    cq[nt][0] += y0 * y0; cq[nt][1] += y1 * y1;
                }
            }
        }
    }
    #pragma unroll
    for (int nt = 0; nt < 4; nt++) {
        #pragma unroll
        for (int j = 0; j < 2; j++) {
            float s = cs[nt][j], q = cq[nt][j];
            #pragma unroll
            for (int o = 4; o < 32; o <<= 1) {
                s += __shfl_xor_sync(0xffffffffu, s, o);
                q += __shfl_xor_sync(0xffffffffu, q, o);
            }
            if (gq == 0) {
                int col = n0 + nt * 8 + tig * 2 + j;
                atomicAdd(&sred[col], s);
                atomicAdd(&sred[128 + col], q);
            }
        }
    }
    __syncthreads();
    if (t < 128) {
        atomicAdd(&g_stats[layer * 256 + t],       sred[t]);
        atomicAdd(&g_stats[layer * 256 + 128 + t], sred[128 + t]);
    }
}

// final layer: norm + relu + attention scores, warp per node; writes g_xh for pooling
__global__ void __launch_bounds__(256) k_norm_scores(const float* __restrict__ gamma,
                                                     const float* __restrict__ beta,
                                                     const float* __restrict__ attn_W,
                                                     const float* __restrict__ attn_b,
                                                     int layer, int n) {
    __shared__ float WsT[CL * 132];   // c-major: WsT[c][k]
    __shared__ float bs[CL];
    int t = threadIdx.x, lane = t & 31, wid = t >> 5;
    for (int i = t; i < 128 * CL; i += 256) {
        int k = i >> 4, c = i & 15;
        WsT[c * 132 + k] = attn_W[i];
    }
    if (t < CL) bs[t] = attn_b[t];
    __syncthreads();
    int node = blockIdx.x * 8 + wid;
    if (node >= n) return;

    const float* st = g_stats + layer * 256;
    float invn = 1.f / (float)n;
    int c0 = lane * 4;
    float4 y   = h4_to_f4(g_yh[node * 32 + lane]);
    float4 ssum = *(const float4*)&st[c0];
    float4 ssq  = *(const float4*)&st[128 + c0];
    float4 ga   = *(const float4*)&gamma[c0];
    float4 be   = *(const float4*)&beta[c0];
    float x[4];
    #pragma unroll
    for (int j = 0; j < 4; j++) {
        float mu  = (&ssum.x)[j] * invn;
        float var = (&ssq.x)[j] * invn - mu * mu;
        float sc  = rsqrtf(var + 1e-5f) * (&ga.x)[j];
        float sh  = (&be.x)[j] - mu * sc;
        x[j] = fmaxf((&y.x)[j] * sc + sh, 0.f);
    }
    g_xh[node * 32 + lane] = f4_to_h4(make_float4(x[0], x[1], x[2], x[3]));

    float p[CL];
    #pragma unroll
    for (int c = 0; c < CL; c++) {
        float4 w = *(const float4*)&WsT[c * 132 + c0];
        p[c] = x[0] * w.x + x[1] * w.y + x[2] * w.z + x[3] * w.w;
    }
    #pragma unroll
    for (int o = 16; o; o >>= 1)
        #pragma unroll
        for (int c = 0; c < CL; c++)
            p[c] += __shfl_xor_sync(0xffffffffu, p[c], o);
    if (lane == 0) {
        float* sp = &g_scores[(size_t)node * CL];
        #pragma unroll
        for (int c = 0; c < CL; c += 4)
            *(float4*)&sp[c] = make_float4(p[c] + bs[c], p[c + 1] + bs[c + 1],
                                           p[c + 2] + bs[c + 2], p[c + 3] + bs[c + 3]);
    }
}

// ---------------- pooling: per-graph max + denom ----------------
__global__ void __launch_bounds__(256) k_poolmax() {
    int g = blockIdx.x, t = threadIdx.x, lane = t & 31, wid = t >> 5;
    int beg = g_goff[g], end = g_goff[g + 1];
    __shared__ float red[CL][9];
    __shared__ float smax[CL];
    float lv[CL];
    #pragma unroll
    for (int c = 0; c < CL; c++) lv[c] = -1e30f;
    for (int i = beg + t; i < end; i += 256) {
        const float4* sp = (const float4*)&g_scores[(size_t)i * CL];
        #pragma unroll
        for (int q = 0; q < 4; q++) {
            float4 s = sp[q];
            lv[4 * q + 0] = fmaxf(lv[4 * q + 0], s.x);
            lv[4 * q + 1] = fmaxf(lv[4 * q + 1], s.y);
            lv[4 * q + 2] = fmaxf(lv[4 * q + 2], s.z);
            lv[4 * q + 3] = fmaxf(lv[4 * q + 3], s.w);
        }
    }
    #pragma unroll
    for (int c = 0; c < CL; c++) {
        float v = lv[c];
        #pragma unroll
        for (int o = 16; o; o >>= 1) v = fmaxf(v, __shfl_xor_sync(0xffffffffu, v, o));
        if (lane == 0) red[c][wid] = v;
    }
    __syncthreads();
    if (t < CL) {
        float v = red[t][0];
        #pragma unroll
        for (int w = 1; w < 8; w++) v = fmaxf(v, red[t][w]);
        smax[t] = v;
    }
    __syncthreads();
    #pragma unroll
    for (int c = 0; c < CL; c++) lv[c] = 0.f;
    for (int i = beg + t; i < end; i += 256) {
        const float4* sp = (const float4*)&g_scores[(size_t)i * CL];
        #pragma unroll
        for (int q = 0; q < 4; q++) {
            float4 s = sp[q];
            lv[4 * q + 0] += expf(s.x - smax[4 * q + 0]);
            lv[4 * q + 1] += expf(s.y - smax[4 * q + 1]);
            lv[4 * q + 2] += expf(s.z - smax[4 * q + 2]);
            lv[4 * q + 3] += expf(s.w - smax[4 * q + 3]);
        }
    }
    #pragma unroll
    for (int c = 0; c < CL; c++) {
        float v = lv[c];
        #pragma unroll
        for (int o = 16; o; o >>= 1) v += __shfl_xor_sync(0xffffffffu, v, o);
        if (lane == 0) red[c][wid] = v;
    }
    __syncthreads();
    if (t < CL) {
        float v = 0.f;
        #pragma unroll
        for (int w = 0; w < 8; w++) v += red[t][w];
        g_pmax[g * CL + t] = smax[t];
        g_pinv[g * CL + t] = 1.f / v;
    }
}

// weighted accumulate (softmax weight computed inline): grid (NG, 8 slices)
__global__ void __launch_bounds__(256) k_poolacc() {
    int g = blockIdx.x, slice = blockIdx.y;
    int beg = g_goff[g], end = g_goff[g + 1], len = end - beg;
    int s0 = beg + (int)(((long long)len * slice) >> 3);
    int s1 = beg + (int)(((long long)len * (slice + 1)) >> 3);
    int t = threadIdx.x;
    int c = t >> 4, h0 = (t & 15) * 8;
    int qb = h0 >> 2;
    float mx = g_pmax[g * CL + c], iv = g_pinv[g * CL + c];
    float acc[8];
    #pragma unroll
    for (int j = 0; j < 8; j++) acc[j] = 0.f;
    for (int i = s0; i < s1; i++) {
        float w = expf(g_scores[(size_t)i * CL + c] - mx) * iv;
        float4 v0 = h4_to_f4(g_xh[i * 32 + qb]);
        float4 v1 = h4_to_f4(g_xh[i * 32 + qb + 1]);
        acc[0] += w * v0.x; acc[1] += w * v0.y; acc[2] += w * v0.z; acc[3] += w * v0.w;
        acc[4] += w * v1.x; acc[5] += w * v1.y; acc[6] += w * v1.z; acc[7] += w * v1.w;
    }
    float* op = &g_clust[((size_t)g * CL + c) * H + h0];
    #pragma unroll
    for (int j = 0; j < 8; j++) atomicAdd(&op[j], acc[j]);
}

// ---------------- final projection ----------------
__global__ void __launch_bounds__(256) k_out(const float* __restrict__ W,
                                             const float* __restrict__ b,
                                             float* __restrict__ out) {
    int row  = blockIdx.x * 8 + (threadIdx.x >> 5);
    int lane = threadIdx.x & 31;
    if (row >= NG * CL) return;
    float4 acc = *(const float4*)&b[lane * 4];
    const float* cl = &g_clust[(size_t)row * H];
    #pragma unroll 4
    for (int k = 0; k < H; k++) {
        float c  = cl[k];
        float4 w = *(const float4*)&W[(size_t)k * ODIM + lane * 4];
        acc.x += c * w.x; acc.y += c * w.y; acc.z += c * w.z; acc.w += c * w.w;
    }
    *(float4*)&out[(size_t)row * ODIM + lane * 4] = acc;
}

// ---------------- launch ----------------
extern "C" void kernel_launch(void* const* d_in, const int* in_sizes, int n_in,
                              void* d_out, int out_size) {
    const float* emb    = (const float*)d_in[0];
    const float* Wl     = (const float*)d_in[1];
    const float* bl     = (const float*)d_in[2];
    const float* Wr     = (const float*)d_in[3];
    const float* gamma  = (const float*)d_in[4];
    const float* beta   = (const float*)d_in[5];
    const float* attn_W = (const float*)d_in[6];
    const float* attn_b = (const float*)d_in[7];
    const float* out_W  = (const float*)d_in[8];
    const float* out_b  = (const float*)d_in[9];
    const int* deg_idx  = (const int*)d_in[10];
    const int* edge     = (const int*)d_in[11];
    const int* batch    = (const int*)d_in[12];
    float* out          = (float*)d_out;

    const int n = NN, e = NE;

    cudaFuncSetAttribute(k_gemm_mma, cudaFuncAttributeMaxDynamicSharedMemorySize,
                         GEMM_SMEM_MMA);

    void* p = nullptr;
    cudaGetSymbolAddress(&p, g_deg);
    cudaMemsetAsync(p, 0, NN * sizeof(int));
    cudaGetSymbolAddress(&p, g_clust);
    cudaMemsetAsync(p, 0, NG * CL * H * sizeof(float));
    cudaGetSymbolAddress(&p, g_stats);
    cudaMemsetAsync(p, 0, 3 * 256 * sizeof(float));

    k_pre<<<B_EMBED + B_SCAT + B_GOFF + B_PREP, 256>>>(emb, deg_idx, edge, edge + e,
                                                       batch, Wl, Wr, n, e);

    int gemmBlocks = (n + 127) / 128;
    for (int l = 0; l < 3; l++) {
        const float* g = (l > 0) ? gamma + (l - 1) * H : gamma;
        const float* be = (l > 0) ? beta + (l - 1) * H : beta;
        k_agg<<<(n * 32 + 255) / 256, 256>>>(g, be, l, n);
        k_gemm_mma<<<gemmBlocks, 256, GEMM_SMEM_MMA>>>(bl + l * H, g, be, l, n);
    }

    k_norm_scores<<<(n + 7) / 8, 256>>>(gamma + 2 * H, beta + 2 * H,
                                        attn_W, attn_b, 2, n);
    k_poolmax<<<NG, 256>>>();
    dim3 pgrid(NG, 8);
    k_poolacc<<<pgrid, 256>>>();
    k_out<<<(NG * CL) / 8, 256>>>(out_W, out_b, out);
}

// round 17
// speedup vs baseline: 1.0349x; 1.0349x over previous
#include <cuda_runtime.h>
#include <cuda_fp16.h>
#include <cstdint>

#define NN 50000
#define NE 800000
#define NG 64
#define H  128
#define CL 16
#define ODIM 128
#define PAD 72    // padded CSR row capacity; in-degree ~Poisson(16), huge margin

// ---------------- scratch (device globals; no allocation allowed) ----------------
__device__ uint2 g_xh[NN * 32];     // fp16 NORMALIZED activation (embedding at layer 0)
__device__ uint2 g_yh[NN * 32];     // fp16 pre-norm GEMM output
__device__ uint2 g_mh[NN * 32];     // fp16 aggregated means
__device__ int   g_deg[NN];         // atomic counter -> final in-degree
__device__ int   g_csrp[NN * PAD];  // padded CSR: PREMULTIPLIED (src*32) row offsets
__device__ float g_scores[NN * CL];
__device__ int   g_goff[NG + 1];
__device__ float g_stats[3 * 256];  // per-layer sum/sumsq slots
__device__ float g_clust[NG * CL * H];
__device__ float g_pmax[NG * CL];
__device__ float g_pinv[NG * CL];
// weights fp16, transposed, packed as u32 pairs along k:
// layout [layer][n][kpair]  (kpair = k/2, 128 pairs, k<128 -> Wl^T, k>=128 -> Wr^T)
__device__ uint32_t g_wth[3 * 128 * 128];

// ---------------- helpers ----------------
__device__ __forceinline__ void mma_f16(float* c, const uint32_t* a, const uint32_t* b) {
    asm volatile(
        "mma.sync.aligned.m16n8k16.row.col.f32.f16.f16.f32 "
        "{%0,%1,%2,%3}, {%4,%5,%6,%7}, {%8,%9}, {%0,%1,%2,%3};"
        : "+f"(c[0]), "+f"(c[1]), "+f"(c[2]), "+f"(c[3])
        : "r"(a[0]), "r"(a[1]), "r"(a[2]), "r"(a[3]), "r"(b[0]), "r"(b[1]));
}

__device__ __forceinline__ uint2 f4_to_h4(float4 v) {
    uint2 u;
    __half2 a = __floats2half2_rn(v.x, v.y);
    __half2 b = __floats2half2_rn(v.z, v.w);
    u.x = *(uint32_t*)&a;
    u.y = *(uint32_t*)&b;
    return u;
}
__device__ __forceinline__ float4 h4_to_f4(uint2 u) {
    float2 a = __half22float2(*(__half2*)&u.x);
    float2 b = __half22float2(*(__half2*)&u.y);
    return make_float4(a.x, a.y, b.x, b.y);
}

// ---------------- merged preamble: embed | scatter(padded CSR) | goff | prep ----------------
#define B_EMBED 6250
#define B_SCAT  3125
#define B_GOFF  196
#define B_PREP  192

__global__ void __launch_bounds__(256) k_pre(const float* __restrict__ emb,
                                             const int* __restrict__ degidx,
                                             const int* __restrict__ src,
                                             const int* __restrict__ dst,
                                             const int* __restrict__ batch,
                                             const float* __restrict__ Wl,
                                             const float* __restrict__ Wr,
                                             int n, int e) {
    int b = blockIdx.x, t = threadIdx.x;
    if (b < B_EMBED) {
        int i = b * 256 + t;
        if (i < n * 32) {
            int node = i >> 5, q = i & 31;
            int d = degidx[node];
            float4 v = ((const float4*)(emb + (size_t)d * H))[q];
            g_xh[i] = f4_to_h4(v);
        }
    } else if (b < B_EMBED + B_SCAT) {
        int i = (b - B_EMBED) * 256 + t;
        if (i < e) {
            int d = dst[i];
            int p = atomicAdd(&g_deg[d], 1);
            if (p < PAD) g_csrp[d * PAD + p] = src[i] * 32;   // premultiplied row offset
        }
    } else if (b < B_EMBED + B_SCAT + B_GOFF) {
        int i = (b - B_EMBED - B_SCAT) * 256 + t;
        if (i < n) {
            int bb = batch[i];
            int bp = (i == 0) ? -1 : batch[i - 1];
            for (int g = bp + 1; g <= bb; g++) g_goff[g] = i;
            if (i == n - 1) {
                for (int g = bb + 1; g <= NG; g++) g_goff[g] = n;
            }
        }
    } else {
        int i = (b - B_EMBED - B_SCAT - B_GOFF) * 256 + t;
        if (i < 3 * 128 * 128) {
            int l = i >> 14, r = i & 16383, nn = r >> 7, kp = r & 127;
            int k = kp * 2;
            float v0, v1;
            if (k < 128) {
                v0 = Wl[l * 16384 + k * 128 + nn];
                v1 = Wl[l * 16384 + (k + 1) * 128 + nn];
            } else {
                v0 = Wr[l * 16384 + (k - 128) * 128 + nn];
                v1 = Wr[l * 16384 + (k - 127) * 128 + nn];
            }
            __half2 h = __floats2half2_rn(v0, v1);
            g_wth[i] = *(uint32_t*)&h;
        }
    }
}

// ---------------- mean aggregation: warp per node, pre-normalized input ----------------
__global__ void __launch_bounds__(256) k_agg(int n) {
    int w    = (blockIdx.x * blockDim.x + threadIdx.x) >> 5;
    int lane = threadIdx.x & 31;
    if (w >= n) return;
    int deg = g_deg[w];
    if (deg > PAD) deg = PAD;
    const int* nb = &g_csrp[w * PAD];
    const uint2* xh = g_xh;
    float4 acc0 = make_float4(0.f, 0.f, 0.f, 0.f);
    float4 acc1 = make_float4(0.f, 0.f, 0.f, 0.f);
    int e = 0;
    for (; e + 1 < deg; e += 2) {
        int s0 = nb[e], s1 = nb[e + 1];
        float4 a = h4_to_f4(xh[s0 + lane]);
        float4 b = h4_to_f4(xh[s1 + lane]);
        acc0.x += a.x; acc0.y += a.y; acc0.z += a.z; acc0.w += a.w;
        acc1.x += b.x; acc1.y += b.y; acc1.z += b.z; acc1.w += b.w;
    }
    if (e < deg) {
        float4 a = h4_to_f4(xh[nb[e] + lane]);
        acc0.x += a.x; acc0.y += a.y; acc0.z += a.z; acc0.w += a.w;
    }
    acc0.x += acc1.x; acc0.y += acc1.y; acc0.z += acc1.z; acc0.w += acc1.w;
    float inv = 1.f / (float)(deg > 1 ? deg : 1);
    acc0.x *= inv; acc0.y *= inv; acc0.z *= inv; acc0.w *= inv;
    g_mh[w * 32 + lane] = f4_to_h4(acc0);
}

// ---------------- per-node normalization: g_yh + stats -> g_xh (fp16) ----------------
__global__ void k_norm(const float* __restrict__ gamma, const float* __restrict__ beta,
                       int layer, int n) {
    int i = blockIdx.x * blockDim.x + threadIdx.x;
    if (i < n * 32) {
        int q = i & 31;
        const float* st = g_stats + layer * 256;
        float invn = 1.f / (float)n;
        float4 y = h4_to_f4(g_yh[i]);
        float4 r;
        #pragma unroll
        for (int j = 0; j < 4; j++) {
            int c = q * 4 + j;
            float mu  = st[c] * invn;
            float var = st[128 + c] * invn - mu * mu;
            float sc  = rsqrtf(var + 1e-5f) * gamma[c];
            float sh  = beta[c] - mu * sc;
            (&r.x)[j] = fmaxf((&y.x)[j] * sc + sh, 0.f);
        }
        g_xh[i] = f4_to_h4(r);
    }
}

// ---------------- mma.sync fp16 GEMM: A exact fp16 (g_mh | g_xh), B fp16 ----------------
#define WST 72
#define PLANE (128 * WST)
#define GEMM_SMEM_MMA (2 * PLANE * 2 + 256 * 4 + 128 * 4)

__global__ void __launch_bounds__(256, 2) k_gemm_mma(const float* __restrict__ bl,
                                                     int layer, int n) {
    extern __shared__ char smraw[];
    __half* As = (__half*)smraw;
    __half* Bs = As + PLANE;
    float* sred   = (float*)(Bs + PLANE);   // [256]
    float* sbias  = sred + 256;             // [128]

    int t = threadIdx.x, lane = t & 31, wid = t >> 5;
    int gq = lane >> 2, tig = lane & 3;
    int rowBase = blockIdx.x * 128;
    int m0 = (wid >> 2) * 64, n0 = (wid & 3) * 32;
    const uint32_t* wth = g_wth + layer * 16384;

    if (t < 128) sbias[t] = bl[t];
    sred[t] = 0.f;

    float acc[4][4][4];
    #pragma unroll
    for (int mt = 0; mt < 4; mt++)
        #pragma unroll
        for (int nt = 0; nt < 4; nt++)
            #pragma unroll
            for (int q = 0; q < 4; q++) acc[mt][nt][q] = 0.f;

    for (int chunk = 0; chunk < 4; chunk++) {
        int qoff = (chunk & 1) * 16;
        const uint2* Asrc = (chunk < 2) ? g_mh : g_xh;
        __syncthreads();
        #pragma unroll
        for (int it = 0; it < 8; it++) {
            int f = t + it * 256;            // 0..2047
            int row = f >> 4, qi = f & 15;
            int grow = rowBase + row;
            uint2 u = make_uint2(0u, 0u);
            if (grow < n) u = Asrc[grow * 32 + qoff + qi];
            int kc = qi * 4;
            *(uint2*)&As[row * WST + kc] = u;
            *(uint2*)&Bs[row * WST + kc] = *(const uint2*)&wth[row * 128 + chunk * 32 + qi * 2];
        }
        __syncthreads();

        #pragma unroll
        for (int ks = 0; ks < 4; ks++) {
            int kb = ks * 16;
            uint32_t bfr[4][2];
            #pragma unroll
            for (int nt = 0; nt < 4; nt++) {
                int brow = n0 + nt * 8 + gq;
                int kc = kb + tig * 2;
                bfr[nt][0] = *(const uint32_t*)&Bs[brow * WST + kc];
                bfr[nt][1] = *(const uint32_t*)&Bs[brow * WST + kc + 8];
            }
            #pragma unroll
            for (int mt = 0; mt < 4; mt++) {
                int arow = m0 + mt * 16 + gq;
                int kc = kb + tig * 2;
                uint32_t a[4];
                a[0] = *(const uint32_t*)&As[arow * WST + kc];
                a[1] = *(const uint32_t*)&As[(arow + 8) * WST + kc];
                a[2] = *(const uint32_t*)&As[arow * WST + kc + 8];
                a[3] = *(const uint32_t*)&As[(arow + 8) * WST + kc + 8];
                #pragma unroll
                for (int nt = 0; nt < 4; nt++) {
                    mma_f16(acc[mt][nt], a, bfr[nt]);
                }
            }
        }
    }

    // epilogue: bias add, store y (fp16), batchnorm partial stats (fp32 exact)
    float cs[4][2], cq[4][2];
    #pragma unroll
    for (int nt = 0; nt < 4; nt++) { cs[nt][0] = cs[nt][1] = cq[nt][0] = cq[nt][1] = 0.f; }
    #pragma unroll
    for (int mt = 0; mt < 4; mt++) {
        #pragma unroll
        for (int r = 0; r < 2; r++) {
            int row = rowBase + m0 + mt * 16 + gq + r * 8;
            if (row < n) {
                #pragma unroll
                for (int nt = 0; nt < 4; nt++) {
                    int col = n0 + nt * 8 + tig * 2;
                    float y0 = acc[mt][nt][r * 2 + 0] + sbias[col];
                    float y1 = acc[mt][nt][r * 2 + 1] + sbias[col + 1];
                    __half2 hp = __floats2half2_rn(y0, y1);
                    ((uint32_t*)g_yh)[(size_t)row * 64 + (col >> 1)] = *(uint32_t*)&hp;
                    cs[nt][0] += y0; cs[nt][1] += y1;
                    cq[nt][0] += y0 * y0; cq[nt][1] += y1 * y1;
                }
            }
        }
    }
    #pragma unroll
    for (int nt = 0; nt < 4; nt++) {
        #pragma unroll
        for (int j = 0; j < 2; j++) {
            float s = cs[nt][j], q = cq[nt][j];
            #pragma unroll
            for (int o = 4; o < 32; o <<= 1) {
                s += __shfl_xor_sync(0xffffffffu, s, o);
                q += __shfl_xor_sync(0xffffffffu, q, o);
            }
            if (gq == 0) {
                int col = n0 + nt * 8 + tig * 2 + j;
                atomicAdd(&sred[col], s);
                atomicAdd(&sred[128 + col], q);
            }
        }
    }
    __syncthreads();
    if (t < 128) {
        atomicAdd(&g_stats[layer * 256 + t],       sred[t]);
        atomicAdd(&g_stats[layer * 256 + 128 + t], sred[128 + t]);
    }
}

// final layer: norm + relu + attention scores, warp per node; writes g_xh for pooling
__global__ void __launch_bounds__(256) k_norm_scores(const float* __restrict__ gamma,
                                                     const float* __restrict__ beta,
                                                     const float* __restrict__ attn_W,
                                                     const float* __restrict__ attn_b,
                                                     int layer, int n) {
    __shared__ float WsT[CL * 132];   // c-major: WsT[c][k]
    __shared__ float bs[CL];
    int t = threadIdx.x, lane = t & 31, wid = t >> 5;
    for (int i = t; i < 128 * CL; i += 256) {
        int k = i >> 4, c = i & 15;
        WsT[c * 132 + k] = attn_W[i];
    }
    if (t < CL) bs[t] = attn_b[t];
    __syncthreads();
    int node = blockIdx.x * 8 + wid;
    if (node >= n) return;

    const float* st = g_stats + layer * 256;
    float invn = 1.f / (float)n;
    int c0 = lane * 4;
    float4 y   = h4_to_f4(g_yh[node * 32 + lane]);
    float4 ssum = *(const float4*)&st[c0];
    float4 ssq  = *(const float4*)&st[128 + c0];
    float4 ga   = *(const float4*)&gamma[c0];
    float4 be   = *(const float4*)&beta[c0];
    float x[4];
    #pragma unroll
    for (int j = 0; j < 4; j++) {
        float mu  = (&ssum.x)[j] * invn;
        float var = (&ssq.x)[j] * invn - mu * mu;
        float sc  = rsqrtf(var + 1e-5f) * (&ga.x)[j];
        float sh  = (&be.x)[j] - mu * sc;
        x[j] = fmaxf((&y.x)[j] * sc + sh, 0.f);
    }
    g_xh[node * 32 + lane] = f4_to_h4(make_float4(x[0], x[1], x[2], x[3]));

    float p[CL];
    #pragma unroll
    for (int c = 0; c < CL; c++) {
        float4 w = *(const float4*)&WsT[c * 132 + c0];
        p[c] = x[0] * w.x + x[1] * w.y + x[2] * w.z + x[3] * w.w;
    }
    #pragma unroll
    for (int o = 16; o; o >>= 1)
        #pragma unroll
        for (int c = 0; c < CL; c++)
            p[c] += __shfl_xor_sync(0xffffffffu, p[c], o);
    if (lane == 0) {
        float* sp = &g_scores[(size_t)node * CL];
        #pragma unroll
        for (int c = 0; c < CL; c += 4)
            *(float4*)&sp[c] = make_float4(p[c] + bs[c], p[c + 1] + bs[c + 1],
                                           p[c + 2] + bs[c + 2], p[c + 3] + bs[c + 3]);
    }
}

// ---------------- pooling: per-graph max + denom ----------------
__global__ void __launch_bounds__(256) k_poolmax() {
    int g = blockIdx.x, t = threadIdx.x, lane = t & 31, wid = t >> 5;
    int beg = g_goff[g], end = g_goff[g + 1];
    __shared__ float red[CL][9];
    __shared__ float smax[CL];
    float lv[CL];
    #pragma unroll
    for (int c = 0; c < CL; c++) lv[c] = -1e30f;
    for (int i = beg + t; i < end; i += 256) {
        const float4* sp = (const float4*)&g_scores[(size_t)i * CL];
        #pragma unroll
        for (int q = 0; q < 4; q++) {
            float4 s = sp[q];
            lv[4 * q + 0] = fmaxf(lv[4 * q + 0], s.x);
            lv[4 * q + 1] = fmaxf(lv[4 * q + 1], s.y);
            lv[4 * q + 2] = fmaxf(lv[4 * q + 2], s.z);
            lv[4 * q + 3] = fmaxf(lv[4 * q + 3], s.w);
        }
    }
    #pragma unroll
    for (int c = 0; c < CL; c++) {
        float v = lv[c];
        #pragma unroll
        for (int o = 16; o; o >>= 1) v = fmaxf(v, __shfl_xor_sync(0xffffffffu, v, o));
        if (lane == 0) red[c][wid] = v;
    }
    __syncthreads();
    if (t < CL) {
        float v = red[t][0];
        #pragma unroll
        for (int w = 1; w < 8; w++) v = fmaxf(v, red[t][w]);
        smax[t] = v;
    }
    __syncthreads();
    #pragma unroll
    for (int c = 0; c < CL; c++) lv[c] = 0.f;
    for (int i = beg + t; i < end; i += 256) {
        const float4* sp = (const float4*)&g_scores[(size_t)i * CL];
        #pragma unroll
        for (int q = 0; q < 4; q++) {
            float4 s = sp[q];
            lv[4 * q + 0] += expf(s.x - smax[4 * q + 0]);
            lv[4 * q + 1] += expf(s.y - smax[4 * q + 1]);
            lv[4 * q + 2] += expf(s.z - smax[4 * q + 2]);
            lv[4 * q + 3] += expf(s.w - smax[4 * q + 3]);
        }
    }
    #pragma unroll
    for (int c = 0; c < CL; c++) {
        float v = lv[c];
        #pragma unroll
        for (int o = 16; o; o >>= 1) v += __shfl_xor_sync(0xffffffffu, v, o);
        if (lane == 0) red[c][wid] = v;
    }
    __syncthreads();
    if (t < CL) {
        float v = 0.f;
        #pragma unroll
        for (int w = 0; w < 8; w++) v += red[t][w];
        g_pmax[g * CL + t] = smax[t];
        g_pinv[g * CL + t] = 1.f / v;
    }
}

// weighted accumulate (softmax weight computed inline): grid (NG, 8 slices)
__global__ void __launch_bounds__(256) k_poolacc() {
    int g = blockIdx.x, slice = blockIdx.y;
    int beg = g_goff[g], end = g_goff[g + 1], len = end - beg;
    int s0 = beg + (int)(((long long)len * slice) >> 3);
    int s1 = beg + (int)(((long long)len * (slice + 1)) >> 3);
    int t = threadIdx.x;
    int c = t >> 4, h0 = (t & 15) * 8;
    int qb = h0 >> 2;
    float mx = g_pmax[g * CL + c], iv = g_pinv[g * CL + c];
    float acc[8];
    #pragma unroll
    for (int j = 0; j < 8; j++) acc[j] = 0.f;
    for (int i = s0; i < s1; i++) {
        float w = expf(g_scores[(size_t)i * CL + c] - mx) * iv;
        float4 v0 = h4_to_f4(g_xh[i * 32 + qb]);
        float4 v1 = h4_to_f4(g_xh[i * 32 + qb + 1]);
        acc[0] += w * v0.x; acc[1] += w * v0.y; acc[2] += w * v0.z; acc[3] += w * v0.w;
        acc[4] += w * v1.x; acc[5] += w * v1.y; acc[6] += w * v1.z; acc[7] += w * v1.w;
    }
    float* op = &g_clust[((size_t)g * CL + c) * H + h0];
    #pragma unroll
    for (int j = 0; j < 8; j++) atomicAdd(&op[j], acc[j]);
}

// ---------------- final projection ----------------
__global__ void __launch_bounds__(256) k_out(const float* __restrict__ W,
                                             const float* __restrict__ b,
                                             float* __restrict__ out) {
    int row  = blockIdx.x * 8 + (threadIdx.x >> 5);
    int lane = threadIdx.x & 31;
    if (row >= NG * CL) return;
    float4 acc = *(const float4*)&b[lane * 4];
    const float* cl = &g_clust[(size_t)row * H];
    #pragma unroll 4
    for (int k = 0; k < H; k++) {
        float c  = cl[k];
        float4 w = *(const float4*)&W[(size_t)k * ODIM + lane * 4];
        acc.x += c * w.x; acc.y += c * w.y; acc.z += c * w.z; acc.w += c * w.w;
    }
    *(float4*)&out[(size_t)row * ODIM + lane * 4] = acc;
}

// ---------------- launch ----------------
extern "C" void kernel_launch(void* const* d_in, const int* in_sizes, int n_in,
                              void* d_out, int out_size) {
    const float* emb    = (const float*)d_in[0];
    const float* Wl     = (const float*)d_in[1];
    const float* bl     = (const float*)d_in[2];
    const float* Wr     = (const float*)d_in[3];
    const float* gamma  = (const float*)d_in[4];
    const float* beta   = (const float*)d_in[5];
    const float* attn_W = (const float*)d_in[6];
    const float* attn_b = (const float*)d_in[7];
    const float* out_W  = (const float*)d_in[8];
    const float* out_b  = (const float*)d_in[9];
    const int* deg_idx  = (const int*)d_in[10];
    const int* edge     = (const int*)d_in[11];
    const int* batch    = (const int*)d_in[12];
    float* out          = (float*)d_out;

    const int n = NN, e = NE;

    cudaFuncSetAttribute(k_gemm_mma, cudaFuncAttributeMaxDynamicSharedMemorySize,
                         GEMM_SMEM_MMA);

    void* p = nullptr;
    cudaGetSymbolAddress(&p, g_deg);
    cudaMemsetAsync(p, 0, NN * sizeof(int));
    cudaGetSymbolAddress(&p, g_clust);
    cudaMemsetAsync(p, 0, NG * CL * H * sizeof(float));
    cudaGetSymbolAddress(&p, g_stats);
    cudaMemsetAsync(p, 0, 3 * 256 * sizeof(float));

    k_pre<<<B_EMBED + B_SCAT + B_GOFF + B_PREP, 256>>>(emb, deg_idx, edge, edge + e,
                                                       batch, Wl, Wr, n, e);

    int gemmBlocks = (n + 127) / 128;
    for (int l = 0; l < 3; l++) {
        k_agg<<<(n * 32 + 255) / 256, 256>>>(n);
        k_gemm_mma<<<gemmBlocks, 256, GEMM_SMEM_MMA>>>(bl + l * H, l, n);
        if (l < 2)
            k_norm<<<(n * 32 + 255) / 256, 256>>>(gamma + l * H, beta + l * H, l, n);
    }

    k_norm_scores<<<(n + 7) / 8, 256>>>(gamma + 2 * H, beta + 2 * H,
                                        attn_W, attn_b, 2, n);
    k_poolmax<<<NG, 256>>>();
    dim3 pgrid(NG, 8);
    k_poolacc<<<pgrid, 256>>>();
    k_out<<<(NG * CL) / 8, 256>>>(out_W, out_b, out);
}